// round 3
// baseline (speedup 1.0000x reference)
#include <cuda_runtime.h>
#include <math.h>

#define L     4096
#define BATCH 16
#define CH    512     // H*E = 8*64
#define TOPK  24      // int(3.0 * ln(4096)) = 24
#define FPSCALE 1048576.0f   // 2^20 fixed point for deterministic accumulation

// ---------------- scratch (device globals; no allocs) ----------------
__device__ float2    d_scr[(size_t)BATCH * 64 * 64 * CH]; // four-step intermediate, 268 MB
__device__ long long d_S[BATCH * L * 2];                  // per-b cross spectrum, fixed point
__device__ float2    d_tw[L];                             // e^{-2pi i m / L}
__device__ float     d_mean[BATCH * L];
__device__ int       d_idx[TOPK];
__device__ float     d_w[BATCH * TOPK];

// ---------------- complex helpers ----------------
__device__ __forceinline__ float2 cadd(float2 a, float2 b){ return make_float2(a.x+b.x, a.y+b.y); }
__device__ __forceinline__ float2 csub(float2 a, float2 b){ return make_float2(a.x-b.x, a.y-b.y); }
__device__ __forceinline__ float2 cmul(float2 a, float2 b){
    return make_float2(a.x*b.x - a.y*b.y, a.x*b.y + a.y*b.x);
}

// ---------------- K0: twiddles + zero accumulators ----------------
__global__ void k_init() {
    int i = blockIdx.x * blockDim.x + threadIdx.x;
    if (i < L) {
        double th = -2.0 * 3.14159265358979323846 * (double)i / (double)L;
        d_tw[i] = make_float2((float)cos(th), (float)sin(th));
    }
    for (int j = i; j < BATCH * L * 2; j += gridDim.x * blockDim.x) d_S[j] = 0;
}

// ---------------- register 8-point DFT, natural order in/out ----------------
__device__ __forceinline__ void dft8(float2* x) {
    const float RS = 0.70710678118654752440f;
    float2 t0=cadd(x[0],x[4]), t4=csub(x[0],x[4]);
    float2 t1=cadd(x[1],x[5]), t5=csub(x[1],x[5]);
    float2 t2=cadd(x[2],x[6]), t6=csub(x[2],x[6]);
    float2 t3=cadd(x[3],x[7]), t7=csub(x[3],x[7]);
    t5 = make_float2(RS*(t5.x+t5.y),  RS*(t5.y-t5.x));     // * W8^1
    t6 = make_float2(t6.y, -t6.x);                          // * W8^2 = -i
    t7 = make_float2(RS*(t7.y-t7.x), -RS*(t7.x+t7.y));      // * W8^3
    float2 v0=cadd(t0,t2), v2=csub(t0,t2), v1=cadd(t1,t3), v3=csub(t1,t3);
    float2 jv3=make_float2(v3.y,-v3.x);
    x[0]=cadd(v0,v1); x[4]=csub(v0,v1);
    x[2]=cadd(v2,jv3); x[6]=csub(v2,jv3);
    float2 u0=cadd(t4,t6), u2=csub(t4,t6), u1=cadd(t5,t7), u3=csub(t5,t7);
    float2 ju3=make_float2(u3.y,-u3.x);
    x[1]=cadd(u0,u1); x[5]=csub(u0,u1);
    x[3]=cadd(u2,ju3); x[7]=csub(u2,ju3);
}

// W64^m for m in [0,49], composed from literal tables (constant-folded under unroll)
__device__ __forceinline__ float2 w64c(int m) {
    const float RS = 0.70710678118654752440f;
    const float2 A[7] = {{1.f,0.f},{RS,-RS},{0.f,-1.f},{-RS,-RS},{-1.f,0.f},{-RS,RS},{0.f,1.f}};
    const float2 Bt[8] = {
        {1.f,0.f},
        {0.99518472667219689f,-0.09801714032956060f},
        {0.98078528040323044f,-0.19509032201612827f},
        {0.95694033573220886f,-0.29028467725446234f},
        {0.92387953251128674f,-0.38268343236508977f},
        {0.88192126434835503f,-0.47139673682599764f},
        {0.83146961230254524f,-0.55557023301960222f},
        {0.77301045336273699f,-0.63439328416364549f}};
    return cmul(A[m>>3], Bt[m&7]);
}

// register 64-pt DFT over r[0..63] (time order). Output digit-swapped:
// r[8*k1 + k2] = X[k1 + 8*k2].
__device__ __forceinline__ void dft64(float2* r) {
    #pragma unroll
    for (int n1 = 0; n1 < 8; n1++) {
        float2 t[8];
        #pragma unroll
        for (int j = 0; j < 8; j++) t[j] = r[n1 + 8*j];
        dft8(t);
        #pragma unroll
        for (int k1 = 0; k1 < 8; k1++) r[n1 + 8*k1] = cmul(t[k1], w64c(n1*k1));
    }
    #pragma unroll
    for (int k1 = 0; k1 < 8; k1++) {
        float2 t[8];
        #pragma unroll
        for (int j = 0; j < 8; j++) t[j] = r[j + 8*k1];
        dft8(t);
        #pragma unroll
        for (int k2 = 0; k2 < 8; k2++) r[8*k1 + k2] = t[k2];
    }
}

// value at r[j] is X[(j>>3) + 8*(j&7)]
#define SWAP8(j) (((j) >> 3) + (((j) & 7) << 3))

// ---------------- Stage 1: z=q+ik, DFT over t2, twiddle, scatter ----------------
// grid: 16 b * 64 t1 * 2 cgroups = 2048 CTAs x 256 threads
__global__ void __launch_bounds__(256, 1) k_stage1(const float* __restrict__ q,
                                                   const float* __restrict__ k) {
    int bx = blockIdx.x;
    int c  = (bx & 1) * 256 + threadIdx.x;
    int t1 = (bx >> 1) & 63;
    int b  = bx >> 7;
    const float* qb = q + ((size_t)b * L) * CH + c;
    const float* kb = k + ((size_t)b * L) * CH + c;
    float2 r[64];
    #pragma unroll
    for (int t2 = 0; t2 < 64; t2++) {
        size_t off = (size_t)(t1 + 64 * t2) * CH;
        r[t2] = make_float2(qb[off], kb[off]);
    }
    dft64(r);
    // store S[b][k1][t1][c] with twiddle W4096^{t1*k1}
    float2* Sb = d_scr + (((size_t)b * 64) * 64 + t1) * CH + c;
    #pragma unroll
    for (int j = 0; j < 64; j++) {
        int k1 = SWAP8(j);
        float2 w = d_tw[t1 * k1];                 // t1*k1 <= 3969 < 4096
        Sb[(size_t)k1 * 64 * CH] = cmul(w, r[j]);
    }
}

// ---------------- Stage 2: DFT over t1, unpack, product, accumulate ----------------
// grid: 16 b * 32 pairs; pair 0 = {k1=0, k1=32} (self-mirrored), pair p = {p, 64-p}
__global__ void __launch_bounds__(256, 1) k_stage2() {
    extern __shared__ float2 zb[];   // [2][64][128] = 128 KB
    int tid    = threadIdx.x;
    int pairid = blockIdx.x & 31;
    int b      = blockIdx.x >> 5;
    int k1A = pairid;
    int k1B = (pairid == 0) ? 32 : 64 - pairid;

    // product-phase identity
    int p2 = tid >> 7;
    int k2 = (tid >> 1) & 63;
    int h  = tid & 1;
    int myk1 = (p2 == 0) ? k1A : k1B;
    int ms, k2m;
    if (pairid == 0) { ms = p2; k2m = (p2 == 0) ? ((64 - k2) & 63) : (63 - k2); }
    else             { ms = 1 - p2; k2m = 63 - k2; }
    int f = myk1 + 64 * k2;

    // DFT-phase identity
    int pa = tid >> 7, ca = tid & 127;
    int kk1 = (pa == 0) ? k1A : k1B;

    float px = 0.f, py = 0.f;
    for (int g = 0; g < 4; g++) {
        const float2* Sp = d_scr + (((size_t)b * 64 + kk1) * 64) * CH + g * 128 + ca;
        float2 r[64];
        #pragma unroll
        for (int t1 = 0; t1 < 64; t1++) r[t1] = Sp[(size_t)t1 * CH];
        dft64(r);
        #pragma unroll
        for (int j = 0; j < 64; j++)
            zb[(pa * 64 + SWAP8(j)) * 128 + ca] = r[j];
        __syncthreads();
        // accumulate P = Q * conj(K) over this 128-channel group
        #pragma unroll 4
        for (int it = 0; it < 64; it++) {
            int c = h * 64 + ((it + k2) & 63);          // bank stagger
            float2 Zf = zb[(p2 * 64 + k2 ) * 128 + c];
            float2 Zr = zb[(ms * 64 + k2m) * 128 + c];
            float qx = 0.5f * (Zf.x + Zr.x), qy =  0.5f * (Zf.y - Zr.y);
            float kx = 0.5f * (Zf.y + Zr.y), ky = -0.5f * (Zf.x - Zr.x);
            px += qx * kx + qy * ky;
            py += qy * kx - qx * ky;
        }
        __syncthreads();
    }
    long long* Sb = d_S + b * L * 2;
    atomicAdd((unsigned long long*)&Sb[2 * f],
              (unsigned long long)(long long)llrintf(px * FPSCALE));
    atomicAdd((unsigned long long*)&Sb[2 * f + 1],
              (unsigned long long)(long long)llrintf(py * FPSCALE));
}

// ---------------- radix-4 Stockham FFT (for K3; 16 CTAs, negligible) ------
__device__ __forceinline__ void fft4096_r4(float2* x0, float2* y0,
                                           const float2* __restrict__ tw, int tid) {
    float2* x = x0;
    float2* y = y0;
    #pragma unroll
    for (int stage = 0; stage < 6; stage++) {
        int s = 1 << (2 * stage);
        #pragma unroll
        for (int uu = 0; uu < 4; uu++) {
            int u  = tid + uu * 256;
            int ps = u & ~(s - 1);
            float2 a = x[u];
            float2 b = x[u + 1024];
            float2 c = x[u + 2048];
            float2 d = x[u + 3072];
            float2 apc = cadd(a, c), amc = csub(a, c);
            float2 bpd = cadd(b, d), bmd = csub(b, d);
            float2 jbmd = make_float2(-bmd.y, bmd.x);
            float2 w1 = tw[ps], w2 = tw[2 * ps], w3 = tw[3 * ps];
            int o = u + 3 * ps;
            y[o]         = cadd(apc, bpd);
            y[o + s]     = cmul(w1, csub(amc, jbmd));
            y[o + 2 * s] = cmul(w2, csub(apc, bpd));
            y[o + 3 * s] = cmul(w3, cadd(amc, jbmd));
        }
        __syncthreads();
        float2* t = x; x = y; y = t;
    }
}

// ---------------- K3: inverse transform -> mean_value ----------------
__global__ void k_irfft() {
    extern __shared__ float2 sm[];
    float2* A   = sm;
    float2* B   = sm + L;
    float2* tws = sm + 2 * L;
    int tid = threadIdx.x;
    int b   = blockIdx.x;
    const long long* Sb = d_S + b * L * 2;
    const float c1 = 1.0f / FPSCALE;
    for (int i = tid; i < L; i += 256) {
        A[i] = make_float2((float)Sb[2 * i] * c1, -(float)Sb[2 * i + 1] * c1);
        tws[i] = d_tw[i];
    }
    __syncthreads();
    fft4096_r4(A, B, tws, tid);
    const float c2 = 1.0f / ((float)L * (float)CH);
    for (int i = tid; i < L; i += 256) d_mean[b * L + i] = A[i].x * c2;
}

// ---------------- K4: top-k over batch-mean + per-batch softmax ----------------
__global__ void k_topk() {
    __shared__ float cm[L];
    __shared__ float rv[256];
    __shared__ int   ri[256];
    __shared__ int   sidx[TOPK];
    int tid = threadIdx.x;
    for (int i = tid; i < L; i += 256) {
        float s = 0.0f;
        #pragma unroll
        for (int b = 0; b < BATCH; b++) s += d_mean[b * L + i];
        cm[i] = s;
    }
    __syncthreads();
    for (int it = 0; it < TOPK; it++) {
        float best = -1e30f; int bi = 0;
        for (int i = tid; i < L; i += 256) {
            float vv = cm[i];
            if (vv > best) { best = vv; bi = i; }
        }
        rv[tid] = best; ri[tid] = bi;
        __syncthreads();
        for (int off = 128; off > 0; off >>= 1) {
            if (tid < off) {
                if (rv[tid + off] > rv[tid] ||
                    (rv[tid + off] == rv[tid] && ri[tid + off] < ri[tid])) {
                    rv[tid] = rv[tid + off]; ri[tid] = ri[tid + off];
                }
            }
            __syncthreads();
        }
        if (tid == 0) { sidx[it] = ri[0]; cm[ri[0]] = -1e30f; }
        __syncthreads();
    }
    if (tid < TOPK) d_idx[tid] = sidx[tid];
    if (tid < BATCH) {
        int b = tid;
        float vals[TOPK]; float mx = -1e30f;
        #pragma unroll
        for (int i = 0; i < TOPK; i++) { vals[i] = d_mean[b * L + sidx[i]]; mx = fmaxf(mx, vals[i]); }
        float ssum = 0.0f;
        #pragma unroll
        for (int i = 0; i < TOPK; i++) { vals[i] = expf(vals[i] - mx); ssum += vals[i]; }
        #pragma unroll
        for (int i = 0; i < TOPK; i++) d_w[b * TOPK + i] = vals[i] / ssum;
    }
}

// ---------------- K5: weighted shifted aggregation ----------------
__global__ void k_agg(const float4* __restrict__ v4, float4* __restrict__ o4) {
    __shared__ int   si[TOPK];
    __shared__ float sw[TOPK];
    int t = blockIdx.x, b = blockIdx.y, tid = threadIdx.x;
    if (tid < TOPK) { si[tid] = d_idx[tid]; sw[tid] = d_w[b * TOPK + tid]; }
    __syncthreads();
    const float4* vb = v4 + (size_t)b * L * 128;
    float4 acc = make_float4(0.f, 0.f, 0.f, 0.f);
    #pragma unroll
    for (int i = 0; i < TOPK; i++) {
        int tt = (t + si[i]) & (L - 1);
        float4 vv = vb[tt * 128 + tid];
        float w = sw[i];
        acc.x += w * vv.x; acc.y += w * vv.y; acc.z += w * vv.z; acc.w += w * vv.w;
    }
    o4[((size_t)b * L + t) * 128 + tid] = acc;
}

// ---------------- launcher ----------------
extern "C" void kernel_launch(void* const* d_in, const int* in_sizes, int n_in,
                              void* d_out, int out_size) {
    const float* q = (const float*)d_in[0];
    const float* k = (const float*)d_in[1];
    const float* v = (const float*)d_in[2];

    const int smem_s2   = 2 * 64 * 128 * sizeof(float2);   // 131072 B
    const int smem_ifft = 3 * L * sizeof(float2);          // 96 KB
    cudaFuncSetAttribute(k_stage2, cudaFuncAttributeMaxDynamicSharedMemorySize, smem_s2);
    cudaFuncSetAttribute(k_irfft,  cudaFuncAttributeMaxDynamicSharedMemorySize, smem_ifft);

    k_init<<<32, 256>>>();
    k_stage1<<<BATCH * 64 * 2, 256>>>(q, k);
    k_stage2<<<BATCH * 32, 256, smem_s2>>>();
    k_irfft<<<BATCH, 256, smem_ifft>>>();
    k_topk<<<1, 256>>>();
    k_agg<<<dim3(L, BATCH), 128>>>((const float4*)v, (float4*)d_out);
}

// round 4
// speedup vs baseline: 1.1082x; 1.1082x over previous
#include <cuda_runtime.h>
#include <math.h>

#define L     4096
#define BATCH 16
#define CH    512     // H*E = 8*64
#define TOPK  24      // int(3.0 * ln(4096)) = 24
#define FPSCALE 1048576.0f   // 2^20 fixed point for deterministic accumulation
#define CPB   8       // channels per CTA in k_fft
#define PAD(i) ((i) + ((i) >> 4))
#define PBUF  4352    // PAD(4095)=4350 -> 4352 float2

// ---------------- scratch (device globals; no allocs) ----------------
__device__ float2    d_z[(size_t)BATCH * CH * L];   // packed z = q + i*k, (B,C,L)
__device__ long long d_S[BATCH * L * 2];            // per-b cross spectrum, fixed point
__device__ float2    d_tw[L];                       // e^{-2pi i m / L}
__device__ float     d_mean[BATCH * L];
__device__ int       d_idx[TOPK];
__device__ float     d_w[BATCH * TOPK];

// ---------------- complex helpers ----------------
__device__ __forceinline__ float2 cadd(float2 a, float2 b){ return make_float2(a.x+b.x, a.y+b.y); }
__device__ __forceinline__ float2 csub(float2 a, float2 b){ return make_float2(a.x-b.x, a.y-b.y); }
__device__ __forceinline__ float2 cmul(float2 a, float2 b){
    return make_float2(a.x*b.x - a.y*b.y, a.x*b.y + a.y*b.x);
}

// ---------------- K0: twiddles + zero accumulators ----------------
__global__ void k_init() {
    int i = blockIdx.x * blockDim.x + threadIdx.x;
    if (i < L) {
        double th = -2.0 * 3.14159265358979323846 * (double)i / (double)L;
        d_tw[i] = make_float2((float)cos(th), (float)sin(th));
    }
    for (int j = i; j < BATCH * L * 2; j += gridDim.x * blockDim.x) d_S[j] = 0;
}

// ---------------- K1: transpose (B,L,C) -> (B,C,L), pack q+ik ----------------
__global__ void k_transpose(const float* __restrict__ q, const float* __restrict__ k) {
    __shared__ float2 tile[32][33];   // [t_local][c_local], padded
    int b  = blockIdx.z;
    int t0 = blockIdx.x * 32;
    int c0 = blockIdx.y * 32;
    int tx = threadIdx.x, ty = threadIdx.y;
    #pragma unroll
    for (int r = 0; r < 4; r++) {
        int t = t0 + ty + r * 8;
        size_t idx = ((size_t)b * L + t) * CH + c0 + tx;   // coalesced over c
        tile[ty + r * 8][tx] = make_float2(q[idx], k[idx]);
    }
    __syncthreads();
    #pragma unroll
    for (int r = 0; r < 4; r++) {
        int c = c0 + ty + r * 8;
        d_z[((size_t)b * CH + c) * L + t0 + tx] = tile[tx][ty + r * 8];  // coalesced over t
    }
}

// ---------------- register 8-point DFT, natural order in/out ----------------
__device__ __forceinline__ void dft8(float2* x) {
    const float RS = 0.70710678118654752440f;
    float2 t0=cadd(x[0],x[4]), t4=csub(x[0],x[4]);
    float2 t1=cadd(x[1],x[5]), t5=csub(x[1],x[5]);
    float2 t2=cadd(x[2],x[6]), t6=csub(x[2],x[6]);
    float2 t3=cadd(x[3],x[7]), t7=csub(x[3],x[7]);
    t5 = make_float2(RS*(t5.x+t5.y),  RS*(t5.y-t5.x));     // * W8^1
    t6 = make_float2(t6.y, -t6.x);                          // * W8^2 = -i
    t7 = make_float2(RS*(t7.y-t7.x), -RS*(t7.x+t7.y));      // * W8^3
    float2 v0=cadd(t0,t2), v2=csub(t0,t2), v1=cadd(t1,t3), v3=csub(t1,t3);
    float2 jv3=make_float2(v3.y,-v3.x);
    x[0]=cadd(v0,v1); x[4]=csub(v0,v1);
    x[2]=cadd(v2,jv3); x[6]=csub(v2,jv3);
    float2 u0=cadd(t4,t6), u2=csub(t4,t6), u1=cadd(t5,t7), u3=csub(t5,t7);
    float2 ju3=make_float2(u3.y,-u3.x);
    x[1]=cadd(u0,u1); x[5]=csub(u0,u1);
    x[3]=cadd(u2,ju3); x[7]=csub(u2,ju3);
}

// Stockham stage store (radix-8): out[u + 7*ps + s*j] = W4096^{ps*j} * r[j]
__device__ __forceinline__ void stage_store8(const float2* r, float2* buf, int u, int s) {
    int ps = u & ~(s - 1);
    float2 w1 = d_tw[ps];
    float2 w2 = d_tw[2 * ps];
    float2 w4 = d_tw[4 * ps];
    float2 w3 = cmul(w1, w2);
    float2 w5 = cmul(w4, w1);
    float2 w6 = cmul(w4, w2);
    float2 w7 = cmul(w4, w3);
    int base = u + 7 * ps;
    buf[PAD(base)]         = r[0];
    buf[PAD(base + s)]     = cmul(w1, r[1]);
    buf[PAD(base + 2*s)]   = cmul(w2, r[2]);
    buf[PAD(base + 3*s)]   = cmul(w3, r[3]);
    buf[PAD(base + 4*s)]   = cmul(w4, r[4]);
    buf[PAD(base + 5*s)]   = cmul(w5, r[5]);
    buf[PAD(base + 6*s)]   = cmul(w6, r[6]);
    buf[PAD(base + 7*s)]   = cmul(w7, r[7]);
}

// ---------------- K2: radix-8 FFT, 512 threads, 8 channels/CTA ----------------
__global__ void __launch_bounds__(512, 2) k_fft() {
    extern __shared__ float2 buf[];   // PBUF float2 = 34816 B
    int tid = threadIdx.x;
    int blk = blockIdx.x;             // 1024 = 16 b * 64 groups
    int b   = blk >> 6;
    int c0  = (blk & 63) * CPB;

    float accx[8], accy[8];
    #pragma unroll
    for (int j = 0; j < 8; j++) { accx[j] = 0.f; accy[j] = 0.f; }

    for (int cc = 0; cc < CPB; cc++) {
        const float2* zr = d_z + ((size_t)(b * CH + c0 + cc)) * L;
        float2 r[8];
        // stage 0 (s=1): global -> regs -> smem
        #pragma unroll
        for (int j = 0; j < 8; j++) r[j] = zr[tid + 512 * j];
        dft8(r);
        stage_store8(r, buf, tid, 1);
        __syncthreads();
        // stage 1 (s=8)
        #pragma unroll
        for (int j = 0; j < 8; j++) r[j] = buf[PAD(tid + 512 * j)];
        __syncthreads();
        dft8(r);
        stage_store8(r, buf, tid, 8);
        __syncthreads();
        // stage 2 (s=64)
        #pragma unroll
        for (int j = 0; j < 8; j++) r[j] = buf[PAD(tid + 512 * j)];
        __syncthreads();
        dft8(r);
        stage_store8(r, buf, tid, 64);
        __syncthreads();
        // stage 3 (s=512, ps=0, twiddles=1): in-place per-thread slots
        #pragma unroll
        for (int j = 0; j < 8; j++) r[j] = buf[PAD(tid + 512 * j)];
        dft8(r);
        #pragma unroll
        for (int j = 0; j < 8; j++) buf[PAD(tid + 512 * j)] = r[j];
        __syncthreads();
        // unpack z=q+ik spectrum, accumulate P = Q * conj(K)
        #pragma unroll
        for (int j = 0; j < 8; j++) {
            int i = tid + 512 * j;
            float2 Zf = buf[PAD(i)];
            float2 Zr = buf[PAD((L - i) & (L - 1))];
            float qx = 0.5f * (Zf.x + Zr.x), qy =  0.5f * (Zf.y - Zr.y);
            float kx = 0.5f * (Zf.y + Zr.y), ky = -0.5f * (Zf.x - Zr.x);
            accx[j] += qx * kx + qy * ky;
            accy[j] += qy * kx - qx * ky;
        }
        __syncthreads();   // protect buf before next channel's stage 0
    }

    long long* Sb = d_S + b * L * 2;
    #pragma unroll
    for (int j = 0; j < 8; j++) {
        int i = tid + 512 * j;
        atomicAdd((unsigned long long*)&Sb[2 * i],
                  (unsigned long long)(long long)llrintf(accx[j] * FPSCALE));
        atomicAdd((unsigned long long*)&Sb[2 * i + 1],
                  (unsigned long long)(long long)llrintf(accy[j] * FPSCALE));
    }
}

// ---------------- radix-4 Stockham FFT (for K3; 16 CTAs, negligible) ------
__device__ __forceinline__ void fft4096_r4(float2* x0, float2* y0,
                                           const float2* __restrict__ tw, int tid) {
    float2* x = x0;
    float2* y = y0;
    #pragma unroll
    for (int stage = 0; stage < 6; stage++) {
        int s = 1 << (2 * stage);
        #pragma unroll
        for (int uu = 0; uu < 4; uu++) {
            int u  = tid + uu * 256;
            int ps = u & ~(s - 1);
            float2 a = x[u];
            float2 b = x[u + 1024];
            float2 c = x[u + 2048];
            float2 d = x[u + 3072];
            float2 apc = cadd(a, c), amc = csub(a, c);
            float2 bpd = cadd(b, d), bmd = csub(b, d);
            float2 jbmd = make_float2(-bmd.y, bmd.x);
            float2 w1 = tw[ps], w2 = tw[2 * ps], w3 = tw[3 * ps];
            int o = u + 3 * ps;
            y[o]         = cadd(apc, bpd);
            y[o + s]     = cmul(w1, csub(amc, jbmd));
            y[o + 2 * s] = cmul(w2, csub(apc, bpd));
            y[o + 3 * s] = cmul(w3, cadd(amc, jbmd));
        }
        __syncthreads();
        float2* t = x; x = y; y = t;
    }
}

// ---------------- K3: inverse transform -> mean_value ----------------
__global__ void k_irfft() {
    extern __shared__ float2 sm[];
    float2* A   = sm;
    float2* B   = sm + L;
    float2* tws = sm + 2 * L;
    int tid = threadIdx.x;
    int b   = blockIdx.x;
    const long long* Sb = d_S + b * L * 2;
    const float c1 = 1.0f / FPSCALE;
    for (int i = tid; i < L; i += 256) {
        A[i] = make_float2((float)Sb[2 * i] * c1, -(float)Sb[2 * i + 1] * c1);
        tws[i] = d_tw[i];
    }
    __syncthreads();
    fft4096_r4(A, B, tws, tid);
    const float c2 = 1.0f / ((float)L * (float)CH);
    for (int i = tid; i < L; i += 256) d_mean[b * L + i] = A[i].x * c2;
}

// ---------------- K4: top-k over batch-mean + per-batch softmax ----------------
__global__ void k_topk() {
    __shared__ float cm[L];
    __shared__ float rv[256];
    __shared__ int   ri[256];
    __shared__ int   sidx[TOPK];
    int tid = threadIdx.x;
    for (int i = tid; i < L; i += 256) {
        float s = 0.0f;
        #pragma unroll
        for (int b = 0; b < BATCH; b++) s += d_mean[b * L + i];
        cm[i] = s;
    }
    __syncthreads();
    for (int it = 0; it < TOPK; it++) {
        float best = -1e30f; int bi = 0;
        for (int i = tid; i < L; i += 256) {
            float vv = cm[i];
            if (vv > best) { best = vv; bi = i; }
        }
        rv[tid] = best; ri[tid] = bi;
        __syncthreads();
        for (int off = 128; off > 0; off >>= 1) {
            if (tid < off) {
                if (rv[tid + off] > rv[tid] ||
                    (rv[tid + off] == rv[tid] && ri[tid + off] < ri[tid])) {
                    rv[tid] = rv[tid + off]; ri[tid] = ri[tid + off];
                }
            }
            __syncthreads();
        }
        if (tid == 0) { sidx[it] = ri[0]; cm[ri[0]] = -1e30f; }
        __syncthreads();
    }
    if (tid < TOPK) d_idx[tid] = sidx[tid];
    if (tid < BATCH) {
        int b = tid;
        float vals[TOPK]; float mx = -1e30f;
        #pragma unroll
        for (int i = 0; i < TOPK; i++) { vals[i] = d_mean[b * L + sidx[i]]; mx = fmaxf(mx, vals[i]); }
        float ssum = 0.0f;
        #pragma unroll
        for (int i = 0; i < TOPK; i++) { vals[i] = expf(vals[i] - mx); ssum += vals[i]; }
        #pragma unroll
        for (int i = 0; i < TOPK; i++) d_w[b * TOPK + i] = vals[i] / ssum;
    }
}

// ---------------- K5: weighted shifted aggregation ----------------
__global__ void k_agg(const float4* __restrict__ v4, float4* __restrict__ o4) {
    __shared__ int   si[TOPK];
    __shared__ float sw[TOPK];
    int t = blockIdx.x, b = blockIdx.y, tid = threadIdx.x;
    if (tid < TOPK) { si[tid] = d_idx[tid]; sw[tid] = d_w[b * TOPK + tid]; }
    __syncthreads();
    const float4* vb = v4 + (size_t)b * L * 128;
    float4 acc = make_float4(0.f, 0.f, 0.f, 0.f);
    #pragma unroll
    for (int i = 0; i < TOPK; i++) {
        int tt = (t + si[i]) & (L - 1);
        float4 vv = vb[tt * 128 + tid];
        float w = sw[i];
        acc.x += w * vv.x; acc.y += w * vv.y; acc.z += w * vv.z; acc.w += w * vv.w;
    }
    o4[((size_t)b * L + t) * 128 + tid] = acc;
}

// ---------------- launcher ----------------
extern "C" void kernel_launch(void* const* d_in, const int* in_sizes, int n_in,
                              void* d_out, int out_size) {
    const float* q = (const float*)d_in[0];
    const float* k = (const float*)d_in[1];
    const float* v = (const float*)d_in[2];

    const int smem_fft  = PBUF * sizeof(float2);     // 34816 B
    const int smem_ifft = 3 * L * sizeof(float2);    // 96 KB
    cudaFuncSetAttribute(k_fft,   cudaFuncAttributeMaxDynamicSharedMemorySize, smem_fft);
    cudaFuncSetAttribute(k_irfft, cudaFuncAttributeMaxDynamicSharedMemorySize, smem_ifft);

    k_init<<<32, 256>>>();
    k_transpose<<<dim3(L / 32, CH / 32, BATCH), dim3(32, 8, 1)>>>(q, k);
    k_fft<<<(BATCH * CH) / CPB, 512, smem_fft>>>();
    k_irfft<<<BATCH, 256, smem_ifft>>>();
    k_topk<<<1, 256>>>();
    k_agg<<<dim3(L, BATCH), 128>>>((const float4*)v, (float4*)d_out);
}